// round 3
// baseline (speedup 1.0000x reference)
#include <cuda_runtime.h>
#include <mma.h>
#include <cstdint>

using namespace nvcuda;

// ---------------------------------------------------------------------------
// Problem constants
// ---------------------------------------------------------------------------
#define BS 4
#define LQ 1024
#define EMBED 256
#define NH 8
#define NL 4
#define NP 16
#define HD 32
#define LEN_V 5440

#define OUT_ELEMS   (BS * LQ * EMBED)
#define LOC_OFFSET  (OUT_ELEMS)
#define LOC_ELEMS   (BS * LQ * NH * NL * NP * 2)
#define ATTN_OFFSET (LOC_OFFSET + LOC_ELEMS)

__constant__ int c_H[NL]     = {64, 32, 16, 8};
__constant__ int c_W[NL]     = {64, 32, 16, 8};
__constant__ int c_start[NL] = {0, 4096, 5120, 5376};

__device__ float g_v[BS * LEN_V * EMBED];   // projected value  ~22.3 MB
__device__ float g_mid[BS * LQ * EMBED];    // pre-W_out         4 MB

// ---------------------------------------------------------------------------
// WMMA tf32x3 GEMM:  C[M,N] = A[M,K] @ B[K,N] + bias[N]
// Block tile 64x64, BK=32, 256 threads (8 warps: 2(m) x 4(n), warp tile 32x16).
// A,B split into tf32 hi/lo planes; D += Ah*Bh + Ah*Bl + Al*Bh (error ~2^-22).
// M,N multiples of 64; K multiple of 32 (all true here).
// ---------------------------------------------------------------------------
#define GBM 64
#define GBN 64
#define GBK 32
#define LDA 36            // A smem row stride (floats): 144B, 16B-multiple
#define LDB 68            // B smem row stride (floats): 272B, 16B-multiple

#define SM_AH 0
#define SM_AL (GBM * LDA)                      // 2304
#define SM_BH (2 * GBM * LDA)                  // 4608
#define SM_BL (2 * GBM * LDA + GBK * LDB)      // 6784
#define SM_FLOATS (2 * GBM * LDA + 2 * GBK * LDB)   // 8960 floats = 35840 B

__device__ __forceinline__ float tf32_hi(float v) {
    return wmma::__float_to_tf32(v);   // cvt.rna.tf32
}

__global__ __launch_bounds__(256) void gemm_wmma_kernel(
    const float* __restrict__ A, const float* __restrict__ B,
    const float* __restrict__ bias, float* __restrict__ C,
    int M, int N, int K)
{
    extern __shared__ float sm[];
    float* Ah = sm + SM_AH;
    float* Al = sm + SM_AL;
    float* Bh = sm + SM_BH;
    float* Bl = sm + SM_BL;

    const int tid = threadIdx.x;
    const int wid = tid >> 5;
    const int wm = wid >> 2;          // 0..1
    const int wn = wid & 3;           // 0..3
    const int m0 = blockIdx.y * GBM;
    const int n0 = blockIdx.x * GBN;

    wmma::fragment<wmma::accumulator, 16, 16, 8, float> acc[2];
    wmma::fill_fragment(acc[0], 0.0f);
    wmma::fill_fragment(acc[1], 0.0f);

    for (int k0 = 0; k0 < K; k0 += GBK) {
        // ---- load + convert A tile: 64 x 32 (512 float4 slots, 2/thread) ----
#pragma unroll
        for (int r = 0; r < 2; r++) {
            int i = tid + r * 256;
            int row = i >> 3;
            int c4 = i & 7;
            float4 v = *(const float4*)(A + (size_t)(m0 + row) * K + k0 + c4 * 4);
            float4 hi, lo;
            hi.x = tf32_hi(v.x); lo.x = tf32_hi(v.x - hi.x);
            hi.y = tf32_hi(v.y); lo.y = tf32_hi(v.y - hi.y);
            hi.z = tf32_hi(v.z); lo.z = tf32_hi(v.z - hi.z);
            hi.w = tf32_hi(v.w); lo.w = tf32_hi(v.w - hi.w);
            *(float4*)(Ah + row * LDA + c4 * 4) = hi;
            *(float4*)(Al + row * LDA + c4 * 4) = lo;
        }
        // ---- load + convert B tile: 32 x 64 (512 float4 slots, 2/thread) ----
#pragma unroll
        for (int r = 0; r < 2; r++) {
            int i = tid + r * 256;
            int row = i >> 4;
            int c4 = i & 15;
            float4 v = *(const float4*)(B + (size_t)(k0 + row) * N + n0 + c4 * 4);
            float4 hi, lo;
            hi.x = tf32_hi(v.x); lo.x = tf32_hi(v.x - hi.x);
            hi.y = tf32_hi(v.y); lo.y = tf32_hi(v.y - hi.y);
            hi.z = tf32_hi(v.z); lo.z = tf32_hi(v.z - hi.z);
            hi.w = tf32_hi(v.w); lo.w = tf32_hi(v.w - hi.w);
            *(float4*)(Bh + row * LDB + c4 * 4) = hi;
            *(float4*)(Bl + row * LDB + c4 * 4) = lo;
        }
        __syncthreads();

        // ---- MMA: 4 k-steps of 8 ----
#pragma unroll
        for (int ks = 0; ks < 4; ks++) {
            wmma::fragment<wmma::matrix_b, 16, 16, 8, wmma::precision::tf32, wmma::row_major> fbh, fbl;
            wmma::load_matrix_sync(fbh, Bh + (ks * 8) * LDB + wn * 16, LDB);
            wmma::load_matrix_sync(fbl, Bl + (ks * 8) * LDB + wn * 16, LDB);
#pragma unroll
            for (int t = 0; t < 2; t++) {
                wmma::fragment<wmma::matrix_a, 16, 16, 8, wmma::precision::tf32, wmma::row_major> fah, fal;
                const int mrow = wm * 32 + t * 16;
                wmma::load_matrix_sync(fah, Ah + mrow * LDA + ks * 8, LDA);
                wmma::load_matrix_sync(fal, Al + mrow * LDA + ks * 8, LDA);
                wmma::mma_sync(acc[t], fah, fbh, acc[t]);
                wmma::mma_sync(acc[t], fah, fbl, acc[t]);
                wmma::mma_sync(acc[t], fal, fbh, acc[t]);
            }
        }
        __syncthreads();
    }

    // ---- epilogue: stage in smem (reuse), add bias, vector store ----
    float* stage = sm;    // 64 x LDB floats = 17.4 KB < 35.8 KB
#pragma unroll
    for (int t = 0; t < 2; t++) {
        wmma::store_matrix_sync(stage + (wm * 32 + t * 16) * LDB + wn * 16,
                                acc[t], LDB, wmma::mem_row_major);
    }
    __syncthreads();

    {
        const int row = tid >> 2;
        const int cbase = (tid & 3) * 16;
        float* crow = C + (size_t)(m0 + row) * N + n0;
#pragma unroll
        for (int j = 0; j < 4; j++) {
            int c = cbase + j * 4;
            float4 v = *(float4*)(stage + row * LDB + c);
            v.x += __ldg(&bias[n0 + c + 0]);
            v.y += __ldg(&bias[n0 + c + 1]);
            v.z += __ldg(&bias[n0 + c + 2]);
            v.w += __ldg(&bias[n0 + c + 3]);
            *(float4*)(crow + c) = v;
        }
    }
}

// ---------------------------------------------------------------------------
// Transform kernel: softmax (64/head) + sampling locations, in place.
// ---------------------------------------------------------------------------
__global__ __launch_bounds__(256) void transform_kernel(
    const float* __restrict__ refp,
    float* __restrict__ loc,
    float* __restrict__ attn)
{
    const int bq = blockIdx.x;
    const int h = threadIdx.x >> 5;
    const int lane = threadIdx.x & 31;

    const float* rp = refp + (size_t)bq * 8;
    const float rx0 = rp[0], rx1 = rp[1], rx2 = rp[2], rx3 = rp[3];
    const float ry0 = rp[4], ry1 = rp[5], ry2 = rp[6], ry3 = rp[7];

    float* ah = attn + ((size_t)bq * NH + h) * 64;
    float v0 = ah[lane];
    float v1 = ah[lane + 32];
    float mx = fmaxf(v0, v1);
#pragma unroll
    for (int o = 16; o > 0; o >>= 1)
        mx = fmaxf(mx, __shfl_xor_sync(0xFFFFFFFFu, mx, o));
    float e0 = expf(v0 - mx);
    float e1 = expf(v1 - mx);
    float s = e0 + e1;
#pragma unroll
    for (int o = 16; o > 0; o >>= 1)
        s += __shfl_xor_sync(0xFFFFFFFFu, s, o);
    float inv = 1.0f / s;
    ah[lane]      = e0 * inv;
    ah[lane + 32] = e1 * inv;

    float* lh = loc + ((size_t)bq * NH + h) * (NL * NP * 2);
#pragma unroll
    for (int r = 0; r < 4; r++) {
        int e = r * 32 + lane;
        int lvl = e >> 5;
        int p = (e >> 1) & 15;
        int c = e & 1;
        float lam = (float)p * (1.0f / 15.0f);
        float pnt;
        if (c == 0) pnt = ((rx0 * lam + rx1) * lam + rx2) * lam + rx3;
        else        pnt = ((ry0 * lam + ry1) * lam + ry2) * lam + ry3;
        float norm = (c == 0) ? (float)c_W[lvl] : (float)c_H[lvl];
        lh[e] = pnt + lh[e] / norm;
    }
}

// ---------------------------------------------------------------------------
// Gather kernel: warp per (b,q,h), lane = channel.
// ---------------------------------------------------------------------------
__global__ __launch_bounds__(256) void gather_kernel(
    const float* __restrict__ v,
    const float* __restrict__ loc,
    const float* __restrict__ attn,
    float* __restrict__ out)
{
    const int bq = blockIdx.x;
    const int b = bq >> 10;
    const int h = threadIdx.x >> 5;
    const int d = threadIdx.x & 31;

    const float* lh = loc  + ((size_t)bq * NH + h) * (NL * NP * 2);
    const float* ah = attn + ((size_t)bq * NH + h) * (NL * NP);
    const float* vb = v + (size_t)b * LEN_V * EMBED + h * HD + d;

    float acc = 0.0f;

#pragma unroll
    for (int lvl = 0; lvl < NL; lvl++) {
        const int W = c_W[lvl];
        const int H = c_H[lvl];
        const float* vl = vb + (size_t)c_start[lvl] * EMBED;
        const float fW = (float)W, fH = (float)H;

#pragma unroll 4
        for (int p = 0; p < NP; p++) {
            int sp = lvl * NP + p;
            float lx = __ldg(&lh[sp * 2 + 0]);
            float ly = __ldg(&lh[sp * 2 + 1]);
            float a  = __ldg(&ah[sp]);

            float x = lx * fW - 0.5f;
            float y = ly * fH - 0.5f;
            float x0f = floorf(x);
            float y0f = floorf(y);
            float wx = x - x0f;
            float wy = y - y0f;
            int x0 = (int)x0f, y0 = (int)y0f;
            int x1 = x0 + 1,   y1 = y0 + 1;

            bool vx0 = (x0 >= 0) & (x0 < W);
            bool vx1 = (x1 >= 0) & (x1 < W);
            bool vy0 = (y0 >= 0) & (y0 < H);
            bool vy1 = (y1 >= 0) & (y1 < H);

            float w00 = (vx0 & vy0) ? (1.0f - wx) * (1.0f - wy) : 0.0f;
            float w10 = (vx1 & vy0) ? wx * (1.0f - wy)          : 0.0f;
            float w01 = (vx0 & vy1) ? (1.0f - wx) * wy          : 0.0f;
            float w11 = (vx1 & vy1) ? wx * wy                   : 0.0f;

            int cx0 = min(max(x0, 0), W - 1);
            int cx1 = min(max(x1, 0), W - 1);
            int cy0 = min(max(y0, 0), H - 1);
            int cy1 = min(max(y1, 0), H - 1);

            float s = 0.0f;
            if (w00 > 0.0f) s = fmaf(w00, __ldg(&vl[(size_t)(cy0 * W + cx0) * EMBED]), s);
            if (w10 > 0.0f) s = fmaf(w10, __ldg(&vl[(size_t)(cy0 * W + cx1) * EMBED]), s);
            if (w01 > 0.0f) s = fmaf(w01, __ldg(&vl[(size_t)(cy1 * W + cx0) * EMBED]), s);
            if (w11 > 0.0f) s = fmaf(w11, __ldg(&vl[(size_t)(cy1 * W + cx1) * EMBED]), s);
            acc = fmaf(a, s, acc);
        }
    }

    out[((size_t)bq * NH + h) * HD + d] = acc;
}

// ---------------------------------------------------------------------------
// Launch
// ---------------------------------------------------------------------------
extern "C" void kernel_launch(void* const* d_in, const int* in_sizes, int n_in,
                              void* d_out, int out_size)
{
    const float* query  = (const float*)d_in[0];
    const float* refp   = (const float*)d_in[1];
    const float* value  = (const float*)d_in[2];
    const float* W_val  = (const float*)d_in[3];
    const float* b_val  = (const float*)d_in[4];
    const float* W_off  = (const float*)d_in[5];
    const float* b_off  = (const float*)d_in[6];
    const float* W_attn = (const float*)d_in[7];
    const float* b_attn = (const float*)d_in[8];
    const float* W_out  = (const float*)d_in[9];
    const float* b_out  = (const float*)d_in[10];

    float* out  = (float*)d_out;
    float* loc  = out + LOC_OFFSET;
    float* attn = out + ATTN_OFFSET;

    float* gv;
    float* gmid;
    cudaGetSymbolAddress((void**)&gv, g_v);
    cudaGetSymbolAddress((void**)&gmid, g_mid);

    const int smem = SM_FLOATS * 4;   // 35840 bytes

    // 1. value projection: [21760,256]
    {
        dim3 grid(EMBED / GBN, (BS * LEN_V) / GBM);
        gemm_wmma_kernel<<<grid, 256, smem>>>(value, W_val, b_val, gv, BS * LEN_V, EMBED, EMBED);
    }
    // 2. sampling offsets -> loc region: [4096,1024]
    {
        dim3 grid(1024 / GBN, (BS * LQ) / GBM);
        gemm_wmma_kernel<<<grid, 256, smem>>>(query, W_off, b_off, loc, BS * LQ, 1024, EMBED);
    }
    // 3. attn logits -> attn region: [4096,512]
    {
        dim3 grid(512 / GBN, (BS * LQ) / GBM);
        gemm_wmma_kernel<<<grid, 256, smem>>>(query, W_attn, b_attn, attn, BS * LQ, 512, EMBED);
    }
    // 4. softmax + location transform
    transform_kernel<<<BS * LQ, 256>>>(refp, loc, attn);

    // 5. bilinear gather + attention-weighted sum
    gather_kernel<<<BS * LQ, 256>>>(gv, loc, attn, gmid);

    // 6. output projection: [4096,256]
    {
        dim3 grid(EMBED / GBN, (BS * LQ) / GBM);
        gemm_wmma_kernel<<<grid, 256, smem>>>(gmid, W_out, b_out, out, BS * LQ, EMBED, EMBED);
    }
}

// round 4
// speedup vs baseline: 1.5155x; 1.5155x over previous
#include <cuda_runtime.h>
#include <cstdint>

// ---------------------------------------------------------------------------
// Problem constants
// ---------------------------------------------------------------------------
#define BS 4
#define LQ 1024
#define EMBED 256
#define NH 8
#define NL 4
#define NP 16
#define HD 32
#define LEN_V 5440

#define OUT_ELEMS   (BS * LQ * EMBED)
#define LOC_OFFSET  (OUT_ELEMS)
#define LOC_ELEMS   (BS * LQ * NH * NL * NP * 2)
#define ATTN_OFFSET (LOC_OFFSET + LOC_ELEMS)

__constant__ int c_H[NL]     = {64, 32, 16, 8};
__constant__ int c_W[NL]     = {64, 32, 16, 8};
__constant__ int c_start[NL] = {0, 4096, 5120, 5376};

__device__ float g_v[BS * LEN_V * EMBED];   // projected value  ~22.3 MB
__device__ float g_mid[BS * LQ * EMBED];    // pre-W_out         4 MB

// ---------------------------------------------------------------------------
// Packed f32x2 helpers (Blackwell FFMA2 — PTX fma.rn.f32x2, sm_100-family)
// ---------------------------------------------------------------------------
__device__ __forceinline__ uint64_t pack2(float x, float y) {
    uint64_t r;
    asm("mov.b64 %0, {%1, %2};" : "=l"(r) : "f"(x), "f"(y));
    return r;
}
__device__ __forceinline__ void unpack2(uint64_t v, float& x, float& y) {
    asm("mov.b64 {%0, %1}, %2;" : "=f"(x), "=f"(y) : "l"(v));
}
__device__ __forceinline__ void ffma2(uint64_t& d, uint64_t a, uint64_t b) {
    asm("fma.rn.f32x2 %0, %1, %2, %0;" : "+l"(d) : "l"(a), "l"(b));
}

// ---------------------------------------------------------------------------
// FFMA2 GEMM:  C[M,N] = A[M,K] @ B[K,N] + bias[N]
// 128x128 block tile, BK=16, 256 threads, 8x8 microtile, packed f32x2 FMA.
// Double-buffered smem. M,N multiples of 128; K multiple of 16.
// ---------------------------------------------------------------------------
#define TBM 128
#define TBN 128
#define TBK 16

__global__ __launch_bounds__(256) void gemm_f32x2_kernel(
    const float* __restrict__ A, const float* __restrict__ B,
    const float* __restrict__ bias, float* __restrict__ C,
    int M, int N, int K)
{
    __shared__ float As[2][TBK][TBM];   // [k][m], 8 KB each
    __shared__ float Bs[2][TBK][TBN];   // [k][n], 8 KB each

    const int tid = threadIdx.x;
    const int tx = tid & 15;            // n microtile index
    const int ty = tid >> 4;            // m microtile index
    const int m0 = blockIdx.y * TBM;
    const int n0 = blockIdx.x * TBN;

    // A load mapping: 512 float4 per tile, 2 per thread
    const int am = tid >> 1;            // will recompute per i below
    (void)am;

    // ---- prologue: load k-tile 0 ----
#pragma unroll
    for (int r = 0; r < 2; r++) {
        int i = tid + r * 256;
        int m = i >> 2;
        int kq = i & 3;
        float4 va = *(const float4*)(A + (size_t)(m0 + m) * K + kq * 4);
        As[0][kq * 4 + 0][m] = va.x;
        As[0][kq * 4 + 1][m] = va.y;
        As[0][kq * 4 + 2][m] = va.z;
        As[0][kq * 4 + 3][m] = va.w;
    }
#pragma unroll
    for (int r = 0; r < 2; r++) {
        int i = tid + r * 256;
        int kk = i >> 5;
        int n4 = i & 31;
        *(float4*)&Bs[0][kk][n4 * 4] =
            *(const float4*)(B + (size_t)kk * N + n0 + n4 * 4);
    }
    __syncthreads();

    uint64_t acc[8][4];
#pragma unroll
    for (int i = 0; i < 8; i++)
#pragma unroll
        for (int j = 0; j < 4; j++) acc[i][j] = 0ull;

    const int KT = K / TBK;
    int cur = 0;

    for (int kt = 0; kt < KT; kt++) {
        // ---- prefetch next k-tile into registers ----
        float4 pa0, pa1, pb0, pb1;
        if (kt + 1 < KT) {
            const int k0 = (kt + 1) * TBK;
            {
                int i = tid;
                pa0 = *(const float4*)(A + (size_t)(m0 + (i >> 2)) * K + k0 + (i & 3) * 4);
                i = tid + 256;
                pa1 = *(const float4*)(A + (size_t)(m0 + (i >> 2)) * K + k0 + (i & 3) * 4);
            }
            {
                int i = tid;
                pb0 = *(const float4*)(B + (size_t)(k0 + (i >> 5)) * N + n0 + (i & 31) * 4);
                i = tid + 256;
                pb1 = *(const float4*)(B + (size_t)(k0 + (i >> 5)) * N + n0 + (i & 31) * 4);
            }
        }

        // ---- compute 16 k-steps ----
#pragma unroll
        for (int k = 0; k < TBK; k++) {
            float4 a0 = *(const float4*)&As[cur][k][ty * 8];
            float4 a1 = *(const float4*)&As[cur][k][ty * 8 + 4];
            ulonglong2 bv0 = *(const ulonglong2*)&Bs[cur][k][tx * 8];
            ulonglong2 bv1 = *(const ulonglong2*)&Bs[cur][k][tx * 8 + 4];
            uint64_t bd[4] = {bv0.x, bv0.y, bv1.x, bv1.y};
            uint64_t ad[8];
            ad[0] = pack2(a0.x, a0.x);
            ad[1] = pack2(a0.y, a0.y);
            ad[2] = pack2(a0.z, a0.z);
            ad[3] = pack2(a0.w, a0.w);
            ad[4] = pack2(a1.x, a1.x);
            ad[5] = pack2(a1.y, a1.y);
            ad[6] = pack2(a1.z, a1.z);
            ad[7] = pack2(a1.w, a1.w);
#pragma unroll
            for (int i = 0; i < 8; i++)
#pragma unroll
                for (int j = 0; j < 4; j++)
                    ffma2(acc[i][j], ad[i], bd[j]);
        }

        // ---- stage prefetched tile into the other buffer ----
        if (kt + 1 < KT) {
            const int nxt = cur ^ 1;
            {
                int i = tid;
                int m = i >> 2, kq = i & 3;
                As[nxt][kq * 4 + 0][m] = pa0.x;
                As[nxt][kq * 4 + 1][m] = pa0.y;
                As[nxt][kq * 4 + 2][m] = pa0.z;
                As[nxt][kq * 4 + 3][m] = pa0.w;
                i = tid + 256;
                m = i >> 2; kq = i & 3;
                As[nxt][kq * 4 + 0][m] = pa1.x;
                As[nxt][kq * 4 + 1][m] = pa1.y;
                As[nxt][kq * 4 + 2][m] = pa1.z;
                As[nxt][kq * 4 + 3][m] = pa1.w;
            }
            {
                int i = tid;
                *(float4*)&Bs[nxt][i >> 5][(i & 31) * 4] = pb0;
                i = tid + 256;
                *(float4*)&Bs[nxt][i >> 5][(i & 31) * 4] = pb1;
            }
            __syncthreads();
            cur = nxt;
        }
    }

    // ---- epilogue: unpack, add bias, vector store ----
    float b8[8];
#pragma unroll
    for (int j = 0; j < 8; j++) b8[j] = __ldg(&bias[n0 + tx * 8 + j]);

#pragma unroll
    for (int i = 0; i < 8; i++) {
        float o[8];
#pragma unroll
        for (int j = 0; j < 4; j++)
            unpack2(acc[i][j], o[2 * j], o[2 * j + 1]);
#pragma unroll
        for (int j = 0; j < 8; j++) o[j] += b8[j];
        float* crow = C + (size_t)(m0 + ty * 8 + i) * N + n0 + tx * 8;
        *(float4*)(crow)     = make_float4(o[0], o[1], o[2], o[3]);
        *(float4*)(crow + 4) = make_float4(o[4], o[5], o[6], o[7]);
    }
}

// ---------------------------------------------------------------------------
// Transform kernel: softmax (64/head) + sampling locations, in place.
// ---------------------------------------------------------------------------
__global__ __launch_bounds__(256) void transform_kernel(
    const float* __restrict__ refp,
    float* __restrict__ loc,
    float* __restrict__ attn)
{
    const int bq = blockIdx.x;
    const int h = threadIdx.x >> 5;
    const int lane = threadIdx.x & 31;

    const float* rp = refp + (size_t)bq * 8;
    const float rx0 = rp[0], rx1 = rp[1], rx2 = rp[2], rx3 = rp[3];
    const float ry0 = rp[4], ry1 = rp[5], ry2 = rp[6], ry3 = rp[7];

    float* ah = attn + ((size_t)bq * NH + h) * 64;
    float v0 = ah[lane];
    float v1 = ah[lane + 32];
    float mx = fmaxf(v0, v1);
#pragma unroll
    for (int o = 16; o > 0; o >>= 1)
        mx = fmaxf(mx, __shfl_xor_sync(0xFFFFFFFFu, mx, o));
    float e0 = expf(v0 - mx);
    float e1 = expf(v1 - mx);
    float s = e0 + e1;
#pragma unroll
    for (int o = 16; o > 0; o >>= 1)
        s += __shfl_xor_sync(0xFFFFFFFFu, s, o);
    float inv = 1.0f / s;
    ah[lane]      = e0 * inv;
    ah[lane + 32] = e1 * inv;

    float* lh = loc + ((size_t)bq * NH + h) * (NL * NP * 2);
#pragma unroll
    for (int r = 0; r < 4; r++) {
        int e = r * 32 + lane;
        int lvl = e >> 5;
        int p = (e >> 1) & 15;
        int c = e & 1;
        float lam = (float)p * (1.0f / 15.0f);
        float pnt;
        if (c == 0) pnt = ((rx0 * lam + rx1) * lam + rx2) * lam + rx3;
        else        pnt = ((ry0 * lam + ry1) * lam + ry2) * lam + ry3;
        float norm = (c == 0) ? (float)c_W[lvl] : (float)c_H[lvl];
        lh[e] = pnt + lh[e] / norm;
    }
}

// ---------------------------------------------------------------------------
// Gather kernel: warp per (b,q,h).
// lane = (corner, channel-group): corner = lane>>3 (4 bilinear corners),
// cg = lane&7 (4 channels each). One LDG.128 warp-instr fetches all 4 corner
// lines per sample. Final shfl_xor(8,16) butterfly sums corner contributions.
// ---------------------------------------------------------------------------
__global__ __launch_bounds__(256) void gather_kernel(
    const float* __restrict__ v,
    const float* __restrict__ loc,
    const float* __restrict__ attn,
    float* __restrict__ out)
{
    const int bq = blockIdx.x;
    const int b = bq >> 10;
    const int h = threadIdx.x >> 5;
    const int lane = threadIdx.x & 31;
    const int corner = lane >> 3;       // 0..3
    const int cg = lane & 7;            // channel group (4 floats)
    const int dx = corner & 1;
    const int dy = corner >> 1;

    const float* lh = loc  + ((size_t)bq * NH + h) * (NL * NP * 2);
    const float* ah = attn + ((size_t)bq * NH + h) * (NL * NP);
    const float* vb = v + (size_t)b * LEN_V * EMBED + h * HD + cg * 4;

    float4 acc = make_float4(0.f, 0.f, 0.f, 0.f);

#pragma unroll
    for (int lvl = 0; lvl < NL; lvl++) {
        const int W = c_W[lvl];
        const int H = c_H[lvl];
        const float* vl = vb + (size_t)c_start[lvl] * EMBED;
        const float fW = (float)W, fH = (float)H;

#pragma unroll 4
        for (int p = 0; p < NP; p++) {
            int sp = lvl * NP + p;
            float lx = __ldg(&lh[sp * 2 + 0]);
            float ly = __ldg(&lh[sp * 2 + 1]);
            float a  = __ldg(&ah[sp]);

            float x = lx * fW - 0.5f;
            float y = ly * fH - 0.5f;
            float x0f = floorf(x);
            float y0f = floorf(y);
            float wx = x - x0f;
            float wy = y - y0f;
            int xi = (int)x0f + dx;
            int yi = (int)y0f + dy;

            bool valid = (xi >= 0) & (xi < W) & (yi >= 0) & (yi < H);
            float wcx = dx ? wx : (1.0f - wx);
            float wcy = dy ? wy : (1.0f - wy);
            float w = valid ? (wcx * wcy * a) : 0.0f;

            if (w != 0.0f) {
                int cx = min(max(xi, 0), W - 1);
                int cy = min(max(yi, 0), H - 1);
                float4 vv = *(const float4*)(vl + (size_t)(cy * W + cx) * EMBED);
                acc.x = fmaf(w, vv.x, acc.x);
                acc.y = fmaf(w, vv.y, acc.y);
                acc.z = fmaf(w, vv.z, acc.z);
                acc.w = fmaf(w, vv.w, acc.w);
            }
        }
    }

    // reduce across the 4 corner groups (lanes differing in bits 3,4)
#pragma unroll
    for (int o = 8; o <= 16; o <<= 1) {
        acc.x += __shfl_xor_sync(0xFFFFFFFFu, acc.x, o);
        acc.y += __shfl_xor_sync(0xFFFFFFFFu, acc.y, o);
        acc.z += __shfl_xor_sync(0xFFFFFFFFu, acc.z, o);
        acc.w += __shfl_xor_sync(0xFFFFFFFFu, acc.w, o);
    }

    if (lane < 8) {
        float* orow = out + ((size_t)bq * NH + h) * HD + cg * 4;
        *(float4*)orow = acc;
    }
}

// ---------------------------------------------------------------------------
// Launch
// ---------------------------------------------------------------------------
extern "C" void kernel_launch(void* const* d_in, const int* in_sizes, int n_in,
                              void* d_out, int out_size)
{
    const float* query  = (const float*)d_in[0];
    const float* refp   = (const float*)d_in[1];
    const float* value  = (const float*)d_in[2];
    const float* W_val  = (const float*)d_in[3];
    const float* b_val  = (const float*)d_in[4];
    const float* W_off  = (const float*)d_in[5];
    const float* b_off  = (const float*)d_in[6];
    const float* W_attn = (const float*)d_in[7];
    const float* b_attn = (const float*)d_in[8];
    const float* W_out  = (const float*)d_in[9];
    const float* b_out  = (const float*)d_in[10];

    float* out  = (float*)d_out;
    float* loc  = out + LOC_OFFSET;
    float* attn = out + ATTN_OFFSET;

    float* gv;
    float* gmid;
    cudaGetSymbolAddress((void**)&gv, g_v);
    cudaGetSymbolAddress((void**)&gmid, g_mid);

    // 1. value projection: [21760,256]
    {
        dim3 grid(EMBED / TBN, (BS * LEN_V) / TBM);
        gemm_f32x2_kernel<<<grid, 256>>>(value, W_val, b_val, gv, BS * LEN_V, EMBED, EMBED);
    }
    // 2. sampling offsets -> loc region: [4096,1024]
    {
        dim3 grid(1024 / TBN, (BS * LQ) / TBM);
        gemm_f32x2_kernel<<<grid, 256>>>(query, W_off, b_off, loc, BS * LQ, 1024, EMBED);
    }
    // 3. attn logits -> attn region: [4096,512]
    {
        dim3 grid(512 / TBN, (BS * LQ) / TBM);
        gemm_f32x2_kernel<<<grid, 256>>>(query, W_attn, b_attn, attn, BS * LQ, 512, EMBED);
    }
    // 4. softmax + location transform
    transform_kernel<<<BS * LQ, 256>>>(refp, loc, attn);

    // 5. bilinear gather + attention-weighted sum
    gather_kernel<<<BS * LQ, 256>>>(gv, loc, attn, gmid);

    // 6. output projection: [4096,256]
    {
        dim3 grid(EMBED / TBN, (BS * LQ) / TBM);
        gemm_f32x2_kernel<<<grid, 256>>>(gmid, W_out, b_out, out, BS * LQ, EMBED, EMBED);
    }
}

// round 5
// speedup vs baseline: 1.6103x; 1.0626x over previous
#include <cuda_runtime.h>
#include <cstdint>

// ---------------------------------------------------------------------------
// Problem constants
// ---------------------------------------------------------------------------
#define BS 4
#define LQ 1024
#define EMBED 256
#define NH 8
#define NL 4
#define NP 16
#define HD 32
#define LEN_V 5440

#define OUT_ELEMS   (BS * LQ * EMBED)
#define LOC_OFFSET  (OUT_ELEMS)
#define LOC_ELEMS   (BS * LQ * NH * NL * NP * 2)
#define ATTN_OFFSET (LOC_OFFSET + LOC_ELEMS)

__constant__ int c_H[NL]     = {64, 32, 16, 8};
__constant__ int c_W[NL]     = {64, 32, 16, 8};
__constant__ int c_start[NL] = {0, 4096, 5120, 5376};

__device__ float g_v[BS * LEN_V * EMBED];   // projected value  ~22.3 MB
__device__ float g_mid[BS * LQ * EMBED];    // pre-W_out         4 MB

// ---------------------------------------------------------------------------
// Packed f32x2 helpers (Blackwell FFMA2 — PTX fma.rn.f32x2)
// ---------------------------------------------------------------------------
__device__ __forceinline__ uint64_t pack2(float x, float y) {
    uint64_t r;
    asm("mov.b64 %0, {%1, %2};" : "=l"(r) : "f"(x), "f"(y));
    return r;
}
__device__ __forceinline__ void unpack2(uint64_t v, float& x, float& y) {
    asm("mov.b64 {%0, %1}, %2;" : "=f"(x), "=f"(y) : "l"(v));
}
__device__ __forceinline__ void ffma2(uint64_t& d, uint64_t a, uint64_t b) {
    asm("fma.rn.f32x2 %0, %1, %2, %0;" : "+l"(d) : "l"(a), "l"(b));
}

// ---------------------------------------------------------------------------
// FFMA2 GEMM, conflict-free smem:
//   C[M,N] = A[M,K] @ B[K,N] + bias[N]
// Block tile 128 x TN, BK=16, 256 threads.
//   TN=128: microtile 8x8 (16x16 thread grid)
//   TN= 64: microtile 4x8 (32x8  thread grid)
// A smem: [k][m] stride 132 (pad) — broadcast reads, low-conflict stores.
// B smem: per-k rows of TN/8 chunks, 10-float chunk stride —
//         banks (10*tx + 2j) mod 32 all distinct => conflict-free LDS.64.
// Accumulators are f32x2 pairs along N. M mult of 128, N mult of TN, K of 16.
// ---------------------------------------------------------------------------
#define TBM 128
#define TBK 16
#define SA  132

template <int TN>
__global__ __launch_bounds__(256) void gemm_f32x2(
    const float* __restrict__ A, const float* __restrict__ B,
    const float* __restrict__ bias, float* __restrict__ C,
    int M, int N, int K)
{
    constexpr int NCH = TN / 8;         // chunks per k-row
    constexpr int SB  = NCH * 10;       // B row stride (floats)
    constexpr int MT  = (TN == 128) ? 8 : 4;   // m per thread
    constexpr int NB4 = TN / 64;        // B float4 loads per thread

    __shared__ float As[2][TBK * SA];
    __shared__ float Bs[2][TBK * SB];

    const int tid = threadIdx.x;
    const int tx  = (TN == 128) ? (tid & 15) : (tid & 7);
    const int ty  = (TN == 128) ? (tid >> 4) : (tid >> 3);
    const int m0  = blockIdx.y * TBM;
    const int n0  = blockIdx.x * TN;

    // ---- staging helpers ----
    auto stage_a = [&](int buf, float4 v, int i) {
        int m = i >> 2, kq = i & 3;
        float* p = &As[buf][(kq * 4) * SA + m];
        p[0 * SA] = v.x; p[1 * SA] = v.y; p[2 * SA] = v.z; p[3 * SA] = v.w;
    };
    auto stage_b = [&](int buf, float4 v, int i) {
        int kk = i / (TN / 4);
        int n4 = i % (TN / 4);
        float* p = &Bs[buf][kk * SB + (n4 >> 1) * 10 + (n4 & 1) * 4];
        *(float2*)(p)     = make_float2(v.x, v.y);
        *(float2*)(p + 2) = make_float2(v.z, v.w);
    };

    // ---- prologue: k-tile 0 ----
#pragma unroll
    for (int r = 0; r < 2; r++) {
        int i = tid + r * 256;
        stage_a(0, *(const float4*)(A + (size_t)(m0 + (i >> 2)) * K + (i & 3) * 4), i);
    }
#pragma unroll
    for (int r = 0; r < NB4; r++) {
        int i = tid + r * 256;
        stage_b(0, *(const float4*)(B + (size_t)(i / (TN / 4)) * N + n0 + (i % (TN / 4)) * 4), i);
    }
    __syncthreads();

    uint64_t acc[MT][4];
#pragma unroll
    for (int i = 0; i < MT; i++)
#pragma unroll
        for (int j = 0; j < 4; j++) acc[i][j] = 0ull;

    const int KT = K / TBK;
    int cur = 0;

    for (int kt = 0; kt < KT; kt++) {
        // ---- prefetch next tile to registers ----
        float4 pa[2], pb[NB4];
        if (kt + 1 < KT) {
            const int k0 = (kt + 1) * TBK;
#pragma unroll
            for (int r = 0; r < 2; r++) {
                int i = tid + r * 256;
                pa[r] = *(const float4*)(A + (size_t)(m0 + (i >> 2)) * K + k0 + (i & 3) * 4);
            }
#pragma unroll
            for (int r = 0; r < NB4; r++) {
                int i = tid + r * 256;
                pb[r] = *(const float4*)(B + (size_t)(k0 + i / (TN / 4)) * N + n0 + (i % (TN / 4)) * 4);
            }
        }

        // ---- compute 16 k-steps ----
#pragma unroll
        for (int k = 0; k < TBK; k++) {
            const float* arow = &As[cur][k * SA + ty * MT];
            float4 a0 = *(const float4*)(arow);
            float4 a1;
            if (TN == 128) a1 = *(const float4*)(arow + 4);

            const uint64_t* bp = (const uint64_t*)&Bs[cur][k * SB + tx * 10];
            uint64_t bd[4];
            bd[0] = bp[0]; bd[1] = bp[1]; bd[2] = bp[2]; bd[3] = bp[3];

            uint64_t ad[MT];
            ad[0] = pack2(a0.x, a0.x);
            ad[1] = pack2(a0.y, a0.y);
            ad[2] = pack2(a0.z, a0.z);
            ad[3] = pack2(a0.w, a0.w);
            if (TN == 128) {
                ad[4] = pack2(a1.x, a1.x);
                ad[5] = pack2(a1.y, a1.y);
                ad[6] = pack2(a1.z, a1.z);
                ad[7] = pack2(a1.w, a1.w);
            }
#pragma unroll
            for (int i = 0; i < MT; i++)
#pragma unroll
                for (int j = 0; j < 4; j++)
                    ffma2(acc[i][j], ad[i], bd[j]);
        }

        // ---- stage prefetched tile ----
        if (kt + 1 < KT) {
            const int nxt = cur ^ 1;
#pragma unroll
            for (int r = 0; r < 2; r++) stage_a(nxt, pa[r], tid + r * 256);
#pragma unroll
            for (int r = 0; r < NB4; r++) stage_b(nxt, pb[r], tid + r * 256);
            __syncthreads();
            cur = nxt;
        }
    }

    // ---- epilogue ----
    float b8[8];
#pragma unroll
    for (int j = 0; j < 8; j++) b8[j] = __ldg(&bias[n0 + tx * 8 + j]);

#pragma unroll
    for (int i = 0; i < MT; i++) {
        float o[8];
#pragma unroll
        for (int j = 0; j < 4; j++)
            unpack2(acc[i][j], o[2 * j], o[2 * j + 1]);
#pragma unroll
        for (int j = 0; j < 8; j++) o[j] += b8[j];
        float* crow = C + (size_t)(m0 + ty * MT + i) * N + n0 + tx * 8;
        *(float4*)(crow)     = make_float4(o[0], o[1], o[2], o[3]);
        *(float4*)(crow + 4) = make_float4(o[4], o[5], o[6], o[7]);
    }
}

// ---------------------------------------------------------------------------
// Transform kernel: softmax (64/head) + sampling locations, in place.
// ---------------------------------------------------------------------------
__global__ __launch_bounds__(256) void transform_kernel(
    const float* __restrict__ refp,
    float* __restrict__ loc,
    float* __restrict__ attn)
{
    const int bq = blockIdx.x;
    const int h = threadIdx.x >> 5;
    const int lane = threadIdx.x & 31;

    const float* rp = refp + (size_t)bq * 8;
    const float rx0 = rp[0], rx1 = rp[1], rx2 = rp[2], rx3 = rp[3];
    const float ry0 = rp[4], ry1 = rp[5], ry2 = rp[6], ry3 = rp[7];

    float* ah = attn + ((size_t)bq * NH + h) * 64;
    float v0 = ah[lane];
    float v1 = ah[lane + 32];
    float mx = fmaxf(v0, v1);
#pragma unroll
    for (int o = 16; o > 0; o >>= 1)
        mx = fmaxf(mx, __shfl_xor_sync(0xFFFFFFFFu, mx, o));
    float e0 = expf(v0 - mx);
    float e1 = expf(v1 - mx);
    float s = e0 + e1;
#pragma unroll
    for (int o = 16; o > 0; o >>= 1)
        s += __shfl_xor_sync(0xFFFFFFFFu, s, o);
    float inv = 1.0f / s;
    ah[lane]      = e0 * inv;
    ah[lane + 32] = e1 * inv;

    float* lh = loc + ((size_t)bq * NH + h) * (NL * NP * 2);
#pragma unroll
    for (int r = 0; r < 4; r++) {
        int e = r * 32 + lane;
        int lvl = e >> 5;
        int p = (e >> 1) & 15;
        int c = e & 1;
        float lam = (float)p * (1.0f / 15.0f);
        float pnt;
        if (c == 0) pnt = ((rx0 * lam + rx1) * lam + rx2) * lam + rx3;
        else        pnt = ((ry0 * lam + ry1) * lam + ry2) * lam + ry3;
        float norm = (c == 0) ? (float)c_W[lvl] : (float)c_H[lvl];
        lh[e] = pnt + lh[e] / norm;
    }
}

// ---------------------------------------------------------------------------
// Gather kernel: warp per (b,q,h); lane = (corner, channel-group).
// ---------------------------------------------------------------------------
__global__ __launch_bounds__(256) void gather_kernel(
    const float* __restrict__ v,
    const float* __restrict__ loc,
    const float* __restrict__ attn,
    float* __restrict__ out)
{
    const int bq = blockIdx.x;
    const int b = bq >> 10;
    const int h = threadIdx.x >> 5;
    const int lane = threadIdx.x & 31;
    const int corner = lane >> 3;
    const int cg = lane & 7;
    const int dx = corner & 1;
    const int dy = corner >> 1;

    const float* lh = loc  + ((size_t)bq * NH + h) * (NL * NP * 2);
    const float* ah = attn + ((size_t)bq * NH + h) * (NL * NP);
    const float* vb = v + (size_t)b * LEN_V * EMBED + h * HD + cg * 4;

    float4 acc = make_float4(0.f, 0.f, 0.f, 0.f);

#pragma unroll
    for (int lvl = 0; lvl < NL; lvl++) {
        const int W = c_W[lvl];
        const int H = c_H[lvl];
        const float* vl = vb + (size_t)c_start[lvl] * EMBED;
        const float fW = (float)W, fH = (float)H;

#pragma unroll 4
        for (int p = 0; p < NP; p++) {
            int sp = lvl * NP + p;
            float lx = __ldg(&lh[sp * 2 + 0]);
            float ly = __ldg(&lh[sp * 2 + 1]);
            float a  = __ldg(&ah[sp]);

            float x = lx * fW - 0.5f;
            float y = ly * fH - 0.5f;
            float x0f = floorf(x);
            float y0f = floorf(y);
            float wx = x - x0f;
            float wy = y - y0f;
            int xi = (int)x0f + dx;
            int yi = (int)y0f + dy;

            bool valid = (xi >= 0) & (xi < W) & (yi >= 0) & (yi < H);
            float wcx = dx ? wx : (1.0f - wx);
            float wcy = dy ? wy : (1.0f - wy);
            float w = valid ? (wcx * wcy * a) : 0.0f;

            if (w != 0.0f) {
                int cx = min(max(xi, 0), W - 1);
                int cy = min(max(yi, 0), H - 1);
                float4 vv = *(const float4*)(vl + (size_t)(cy * W + cx) * EMBED);
                acc.x = fmaf(w, vv.x, acc.x);
                acc.y = fmaf(w, vv.y, acc.y);
                acc.z = fmaf(w, vv.z, acc.z);
                acc.w = fmaf(w, vv.w, acc.w);
            }
        }
    }

#pragma unroll
    for (int o = 8; o <= 16; o <<= 1) {
        acc.x += __shfl_xor_sync(0xFFFFFFFFu, acc.x, o);
        acc.y += __shfl_xor_sync(0xFFFFFFFFu, acc.y, o);
        acc.z += __shfl_xor_sync(0xFFFFFFFFu, acc.z, o);
        acc.w += __shfl_xor_sync(0xFFFFFFFFu, acc.w, o);
    }

    if (lane < 8) {
        float* orow = out + ((size_t)bq * NH + h) * HD + cg * 4;
        *(float4*)orow = acc;
    }
}

// ---------------------------------------------------------------------------
// Launch
// ---------------------------------------------------------------------------
extern "C" void kernel_launch(void* const* d_in, const int* in_sizes, int n_in,
                              void* d_out, int out_size)
{
    const float* query  = (const float*)d_in[0];
    const float* refp   = (const float*)d_in[1];
    const float* value  = (const float*)d_in[2];
    const float* W_val  = (const float*)d_in[3];
    const float* b_val  = (const float*)d_in[4];
    const float* W_off  = (const float*)d_in[5];
    const float* b_off  = (const float*)d_in[6];
    const float* W_attn = (const float*)d_in[7];
    const float* b_attn = (const float*)d_in[8];
    const float* W_out  = (const float*)d_in[9];
    const float* b_out  = (const float*)d_in[10];

    float* out  = (float*)d_out;
    float* loc  = out + LOC_OFFSET;
    float* attn = out + ATTN_OFFSET;

    float* gv;
    float* gmid;
    cudaGetSymbolAddress((void**)&gv, g_v);
    cudaGetSymbolAddress((void**)&gmid, g_mid);

    // 1. value projection: [21760,256] (TN=128 -> 340 CTAs)
    {
        dim3 grid(EMBED / 128, (BS * LEN_V) / TBM);
        gemm_f32x2<128><<<grid, 256>>>(value, W_val, b_val, gv, BS * LEN_V, EMBED, EMBED);
    }
    // 2. sampling offsets -> loc region: [4096,1024] (TN=128 -> 256 CTAs)
    {
        dim3 grid(1024 / 128, (BS * LQ) / TBM);
        gemm_f32x2<128><<<grid, 256>>>(query, W_off, b_off, loc, BS * LQ, 1024, EMBED);
    }
    // 3. attn logits -> attn region: [4096,512] (TN=64 -> 256 CTAs)
    {
        dim3 grid(512 / 64, (BS * LQ) / TBM);
        gemm_f32x2<64><<<grid, 256>>>(query, W_attn, b_attn, attn, BS * LQ, 512, EMBED);
    }
    // 4. softmax + location transform
    transform_kernel<<<BS * LQ, 256>>>(refp, loc, attn);

    // 5. bilinear gather + attention-weighted sum
    gather_kernel<<<BS * LQ, 256>>>(gv, loc, attn, gmid);

    // 6. output projection: [4096,256] (TN=64 -> 128 CTAs)
    {
        dim3 grid(EMBED / 64, (BS * LQ) / TBM);
        gemm_f32x2<64><<<grid, 256>>>(gmid, W_out, b_out, out, BS * LQ, EMBED, EMBED);
    }
}